// round 16
// baseline (speedup 1.0000x reference)
#include <cuda_runtime.h>
#include <cstdint>

// Inputs (bound by element count, not position):
//   x       float32 [1000000, 2]        -> 2,000,000 elems
//   phases  float32 [16000000]          -> 16,000,000 elems
//   edges   int64-or-int32 [16000000,2] -> 32,000,000 elems
// Output: float32 [1000000, 2]
//
// FINAL (measured R2-R13): scatter kernel is bound by L1tex wavefront + L2
// REDG lane throughput — 4 random 8B ops/edge (2 gathers + 2 red.v2) is
// formulation-minimal. Model: 32M gather-lanes (~1 wf/cyc/SM) + 32M REDG
// lanes (1.29 cyc/lane spread) ~= 229us; best measured 229.2/229.3us @
// L2=95% across independent holds. Run-to-run noise +/-4us. Rejected by
// measurement or traffic accounting: edges/thread {1,4}, 512-blocks,
// .cg/.ca policy swaps, batched reds, D2D-memcpy init, CSR/binning,
// smem privatization, red.v4 merging (destinations are distinct nodes).

static constexpr int N_NODES = 1000000;
static constexpr int N_EDGES = 16000000;

// ---------------------------------------------------------------------------
// out = x (out arrives poisoned). 500,000 float4. DRAM-bound, ~2.9us.
// ---------------------------------------------------------------------------
__global__ void init_out_kernel(const float4* __restrict__ x4,
                                float4* __restrict__ out4,
                                int n4) {
    int i = blockIdx.x * blockDim.x + threadIdx.x;
    if (i < n4) out4[i] = x4[i];
}

// ---------------------------------------------------------------------------
// Streaming loads: evict-first (.cs) keeps the hot x/out set resident in L2.
// ---------------------------------------------------------------------------
__device__ __forceinline__ int4 ldg_cs_int4(const int4* p) {
    int4 r;
    asm volatile("ld.global.cs.v4.s32 {%0,%1,%2,%3}, [%4];"
                 : "=r"(r.x), "=r"(r.y), "=r"(r.z), "=r"(r.w) : "l"(p));
    return r;
}
__device__ __forceinline__ float2 ldg_cs_float2(const float2* p) {
    float2 r;
    asm volatile("ld.global.cs.v2.f32 {%0,%1}, [%2];"
                 : "=f"(r.x), "=f"(r.y) : "l"(p));
    return r;
}
__device__ __forceinline__ longlong2 ldg_cs_ll2(const longlong2* p) {
    longlong2 r;
    asm volatile("ld.global.cs.v2.s64 {%0,%1}, [%2];"
                 : "=l"(r.x), "=l"(r.y) : "l"(p));
    return r;
}

__device__ __forceinline__ void rotate_scatter(float2 hu, float2 hv,
                                               float s, float c,
                                               float* du, float* dv) {
    // t_u = R(+p) h_u -> out[v],  t_v = R(-p) h_v -> out[u]
    float tu0 = fmaf(hu.x, c, -hu.y * s);
    float tu1 = fmaf(hu.x, s,  hu.y * c);
    float tv0 = fmaf(hv.x, c,  hv.y * s);
    float tv1 = fmaf(hv.y, c, -hv.x * s);
    asm volatile("red.global.add.v2.f32 [%0], {%1, %2};"
                 :: "l"(dv), "f"(tu0), "f"(tu1) : "memory");
    asm volatile("red.global.add.v2.f32 [%0], {%1, %2};"
                 :: "l"(du), "f"(tv0), "f"(tv1) : "memory");
}

// ---------------------------------------------------------------------------
// 2 edges/thread, 256-thread blocks (best-measured config).
// Grid divides exactly (8M threads / 256), so no bounds guard.
// Edge dtype detected in-kernel from the int64 view (genuine int64 indices
// are < 1e6; int32 pairs misread as int64 are ~4e15, so 3 probes suffice).
// ---------------------------------------------------------------------------
__global__ void __launch_bounds__(256)
edge_scatter_kernel(const float2* __restrict__ x,
                    const float* __restrict__ phases,
                    const void* __restrict__ edges_raw,
                    float* __restrict__ out) {
    __shared__ int s_mode;  // 1 = int32 pairs, 2 = int64 pairs
    if (threadIdx.x == 0) {
        const long long* e64 = (const long long*)edges_raw;
        int mode = 2;
        #pragma unroll
        for (int i = 1; i < 7; i += 2) {
            long long val = __ldg(&e64[i]);
            if (val < 0 || val >= (long long)N_NODES) { mode = 1; break; }
        }
        s_mode = mode;
    }
    __syncthreads();
    int mode = s_mode;

    int gid = blockIdx.x * blockDim.x + threadIdx.x;   // [0, N_EDGES/2)

    float2 ph = ldg_cs_float2(((const float2*)phases) + gid);
    float s0, c0, s1, c1;
    __sincosf(ph.x, &s0, &c0);
    __sincosf(ph.y, &s1, &c1);

    if (mode == 1) {
        int4 e = ldg_cs_int4(((const int4*)edges_raw) + gid);  // u0,v0,u1,v1
        float2 hu0 = __ldg(&x[e.x]);
        float2 hv0 = __ldg(&x[e.y]);
        float2 hu1 = __ldg(&x[e.z]);
        float2 hv1 = __ldg(&x[e.w]);
        rotate_scatter(hu0, hv0, s0, c0, out + 2 * e.x, out + 2 * e.y);
        rotate_scatter(hu1, hv1, s1, c1, out + 2 * e.z, out + 2 * e.w);
    } else {
        longlong2 e0 = ldg_cs_ll2(((const longlong2*)edges_raw) + 2 * gid);
        longlong2 e1 = ldg_cs_ll2(((const longlong2*)edges_raw) + 2 * gid + 1);
        float2 hu0 = __ldg(&x[e0.x]);
        float2 hv0 = __ldg(&x[e0.y]);
        float2 hu1 = __ldg(&x[e1.x]);
        float2 hv1 = __ldg(&x[e1.y]);
        rotate_scatter(hu0, hv0, s0, c0, out + 2 * e0.x, out + 2 * e0.y);
        rotate_scatter(hu1, hv1, s1, c1, out + 2 * e1.x, out + 2 * e1.y);
    }
}

extern "C" void kernel_launch(void* const* d_in, const int* in_sizes, int n_in,
                              void* d_out, int out_size) {
    const float* x      = nullptr;
    const float* phases = nullptr;
    const void*  edges  = nullptr;
    for (int i = 0; i < n_in; i++) {
        if      (in_sizes[i] == 2 * N_NODES) x      = (const float*)d_in[i];
        else if (in_sizes[i] == N_EDGES)     phases = (const float*)d_in[i];
        else if (in_sizes[i] == 2 * N_EDGES) edges  = d_in[i];
    }
    float* out = (float*)d_out;

    int n4 = (N_NODES * 2) / 4;  // 500,000
    init_out_kernel<<<(n4 + 255) / 256, 256>>>((const float4*)x, (float4*)out, n4);

    edge_scatter_kernel<<<(N_EDGES / 2) / 256, 256>>>((const float2*)x, phases, edges, out);
}

// round 17
// speedup vs baseline: 1.0175x; 1.0175x over previous
#include <cuda_runtime.h>
#include <cstdint>

// Inputs (bound by element count, not position):
//   x       float32 [1000000, 2]        -> 2,000,000 elems
//   phases  float32 [16000000]          -> 16,000,000 elems
//   edges   int64-or-int32 [16000000,2] -> 32,000,000 elems
// Output: float32 [1000000, 2]
//
// FINAL (measured R2-R16): scatter kernel is bound by L1tex wavefront + L2
// REDG lane throughput — 4 random 8B ops/edge (2 gathers + 2 red.v2) is
// formulation-minimal. Model: 32M gather-lanes (~1 wf/cyc/SM) + 32M REDG
// lanes (1.29 cyc/lane spread) ~= 229us; measured 229.2-232.8us @ L2=94-95%
// across four independent holds of this exact source. Rejected by
// measurement or slot accounting: edges/thread {1,4}, 512-blocks, .cg/.ca
// policy swaps, batched reds, D2D-memcpy init (R10: -7us regression),
// CSR/binning, smem privatization, red.v4 merging (8B-aligned distinct
// destinations), occupancy capping.

static constexpr int N_NODES = 1000000;
static constexpr int N_EDGES = 16000000;

// ---------------------------------------------------------------------------
// out = x (out arrives poisoned). 500,000 float4. DRAM-bound, ~2.9us.
// ---------------------------------------------------------------------------
__global__ void init_out_kernel(const float4* __restrict__ x4,
                                float4* __restrict__ out4,
                                int n4) {
    int i = blockIdx.x * blockDim.x + threadIdx.x;
    if (i < n4) out4[i] = x4[i];
}

// ---------------------------------------------------------------------------
// Streaming loads: evict-first (.cs) keeps the hot x/out set resident in L2.
// ---------------------------------------------------------------------------
__device__ __forceinline__ int4 ldg_cs_int4(const int4* p) {
    int4 r;
    asm volatile("ld.global.cs.v4.s32 {%0,%1,%2,%3}, [%4];"
                 : "=r"(r.x), "=r"(r.y), "=r"(r.z), "=r"(r.w) : "l"(p));
    return r;
}
__device__ __forceinline__ float2 ldg_cs_float2(const float2* p) {
    float2 r;
    asm volatile("ld.global.cs.v2.f32 {%0,%1}, [%2];"
                 : "=f"(r.x), "=f"(r.y) : "l"(p));
    return r;
}
__device__ __forceinline__ longlong2 ldg_cs_ll2(const longlong2* p) {
    longlong2 r;
    asm volatile("ld.global.cs.v2.s64 {%0,%1}, [%2];"
                 : "=l"(r.x), "=l"(r.y) : "l"(p));
    return r;
}

__device__ __forceinline__ void rotate_scatter(float2 hu, float2 hv,
                                               float s, float c,
                                               float* du, float* dv) {
    // t_u = R(+p) h_u -> out[v],  t_v = R(-p) h_v -> out[u]
    float tu0 = fmaf(hu.x, c, -hu.y * s);
    float tu1 = fmaf(hu.x, s,  hu.y * c);
    float tv0 = fmaf(hv.x, c,  hv.y * s);
    float tv1 = fmaf(hv.y, c, -hv.x * s);
    asm volatile("red.global.add.v2.f32 [%0], {%1, %2};"
                 :: "l"(dv), "f"(tu0), "f"(tu1) : "memory");
    asm volatile("red.global.add.v2.f32 [%0], {%1, %2};"
                 :: "l"(du), "f"(tv0), "f"(tv1) : "memory");
}

// ---------------------------------------------------------------------------
// 2 edges/thread, 256-thread blocks (best-measured config).
// Grid divides exactly (8M threads / 256), so no bounds guard.
// Edge dtype detected in-kernel from the int64 view (genuine int64 indices
// are < 1e6; int32 pairs misread as int64 are ~4e15, so 3 probes suffice).
// ---------------------------------------------------------------------------
__global__ void __launch_bounds__(256)
edge_scatter_kernel(const float2* __restrict__ x,
                    const float* __restrict__ phases,
                    const void* __restrict__ edges_raw,
                    float* __restrict__ out) {
    __shared__ int s_mode;  // 1 = int32 pairs, 2 = int64 pairs
    if (threadIdx.x == 0) {
        const long long* e64 = (const long long*)edges_raw;
        int mode = 2;
        #pragma unroll
        for (int i = 1; i < 7; i += 2) {
            long long val = __ldg(&e64[i]);
            if (val < 0 || val >= (long long)N_NODES) { mode = 1; break; }
        }
        s_mode = mode;
    }
    __syncthreads();
    int mode = s_mode;

    int gid = blockIdx.x * blockDim.x + threadIdx.x;   // [0, N_EDGES/2)

    float2 ph = ldg_cs_float2(((const float2*)phases) + gid);
    float s0, c0, s1, c1;
    __sincosf(ph.x, &s0, &c0);
    __sincosf(ph.y, &s1, &c1);

    if (mode == 1) {
        int4 e = ldg_cs_int4(((const int4*)edges_raw) + gid);  // u0,v0,u1,v1
        float2 hu0 = __ldg(&x[e.x]);
        float2 hv0 = __ldg(&x[e.y]);
        float2 hu1 = __ldg(&x[e.z]);
        float2 hv1 = __ldg(&x[e.w]);
        rotate_scatter(hu0, hv0, s0, c0, out + 2 * e.x, out + 2 * e.y);
        rotate_scatter(hu1, hv1, s1, c1, out + 2 * e.z, out + 2 * e.w);
    } else {
        longlong2 e0 = ldg_cs_ll2(((const longlong2*)edges_raw) + 2 * gid);
        longlong2 e1 = ldg_cs_ll2(((const longlong2*)edges_raw) + 2 * gid + 1);
        float2 hu0 = __ldg(&x[e0.x]);
        float2 hv0 = __ldg(&x[e0.y]);
        float2 hu1 = __ldg(&x[e1.x]);
        float2 hv1 = __ldg(&x[e1.y]);
        rotate_scatter(hu0, hv0, s0, c0, out + 2 * e0.x, out + 2 * e0.y);
        rotate_scatter(hu1, hv1, s1, c1, out + 2 * e1.x, out + 2 * e1.y);
    }
}

extern "C" void kernel_launch(void* const* d_in, const int* in_sizes, int n_in,
                              void* d_out, int out_size) {
    const float* x      = nullptr;
    const float* phases = nullptr;
    const void*  edges  = nullptr;
    for (int i = 0; i < n_in; i++) {
        if      (in_sizes[i] == 2 * N_NODES) x      = (const float*)d_in[i];
        else if (in_sizes[i] == N_EDGES)     phases = (const float*)d_in[i];
        else if (in_sizes[i] == 2 * N_EDGES) edges  = d_in[i];
    }
    float* out = (float*)d_out;

    int n4 = (N_NODES * 2) / 4;  // 500,000
    init_out_kernel<<<(n4 + 255) / 256, 256>>>((const float4*)x, (float4*)out, n4);

    edge_scatter_kernel<<<(N_EDGES / 2) / 256, 256>>>((const float2*)x, phases, edges, out);
}